// round 9
// baseline (speedup 1.0000x reference)
#include <cuda_runtime.h>

#define N_USERS 100000
#define N_ITEMS 50000
#define N_NODES 150000
#define KDIM    64
#define N_EDGES 2000000
#define BATCH   4096
#define NEG_SLOPE 0.01f
#define EPSV    1e-12f

#define SCAN_ELEMS 4096
#define SCAN_BLOCKS ((N_NODES + SCAN_ELEMS - 1) / SCAN_ELEMS)   // 37

#define GB_GATHER ((N_NODES * 32) / 256)          // 18750 gather blocks
#define DOT_BLOCKS (BATCH / 8)                     // 512 dot blocks

typedef unsigned long long u64;

__device__ __forceinline__ u64 dup2(float v) {
    u64 r; asm("mov.b64 %0, {%1, %1};" : "=l"(r) : "f"(v)); return r;
}
__device__ __forceinline__ u64 pack2(float lo, float hi) {
    u64 r; asm("mov.b64 %0, {%1, %2};" : "=l"(r) : "f"(lo), "f"(hi)); return r;
}
__device__ __forceinline__ float2 unpack2(u64 v) {
    float2 f; asm("mov.b64 {%0, %1}, %2;" : "=f"(f.x), "=f"(f.y) : "l"(v)); return f;
}
__device__ __forceinline__ void fma2(u64& d, u64 a, u64 b) {
    asm("fma.rn.f32x2 %0, %1, %2, %0;" : "+l"(d) : "l"(a), "l"(b));
}

// ---------------- scratch ----------------------------------------------------
__device__ float g_X[(size_t)N_NODES * KDIM];
__device__ float g_Y[(size_t)N_NODES * KDIM];
__device__ float g_S[(size_t)N_NODES * KDIM];
__device__ float g_wsum[N_NODES];
__device__ int   g_cnt[N_NODES];        // zeroed by scan kernel for next call
__device__ int   g_off[N_NODES + 1];
__device__ int   g_fill[N_NODES];
__device__ int2  g_edge[N_EDGES];
__device__ int   g_sflag[SCAN_BLOCKS];  // zeroed by k_init each call
__device__ int   g_spfx[SCAN_BLOCKS];

// ---------------- init: X = concat(Gu, Gi); zero scan flags ----------------
__global__ void k_init(const float* __restrict__ Gu, const float* __restrict__ Gi) {
    int i = blockIdx.x * blockDim.x + threadIdx.x;
    const int total  = N_NODES * KDIM / 4;
    const int usplit = N_USERS * KDIM / 4;
    if (i < SCAN_BLOCKS) g_sflag[i] = 0;
    if (i >= total) return;
    float4 v = (i < usplit) ? ((const float4*)Gu)[i] : ((const float4*)Gi)[i - usplit];
    ((float4*)g_X)[i] = v;
}

// ---------------- CSR build -------------------------------------------------
__global__ void k_hist(const int* __restrict__ dst) {
    int t = blockIdx.x * blockDim.x + threadIdx.x;
    int e = t * 4;
    if (e + 3 < N_EDGES) {
        int4 d4 = *(const int4*)&dst[e];
        atomicAdd(&g_cnt[d4.x], 1);
        atomicAdd(&g_cnt[d4.y], 1);
        atomicAdd(&g_cnt[d4.z], 1);
        atomicAdd(&g_cnt[d4.w], 1);
    } else {
        for (int i = e; i < N_EDGES; i++) atomicAdd(&g_cnt[dst[i]], 1);
    }
}

// single-pass chained scan: 37 co-resident blocks; exclusive prefix of g_cnt
// into g_off/g_fill; zeroes g_cnt behind itself.
__global__ void __launch_bounds__(1024) k_scan37() {
    __shared__ int wsm[33];
    __shared__ int s_prefix;
    int b = blockIdx.x;
    int tid = threadIdx.x;
    int lane = tid & 31, wid = tid >> 5;
    int base = b * SCAN_ELEMS + tid * 4;

    int v[4];
    int t = 0;
#pragma unroll
    for (int j = 0; j < 4; j++) {
        int g = base + j;
        v[j] = (g < N_NODES) ? g_cnt[g] : 0;
        t += v[j];
    }
    int inc = t;
#pragma unroll
    for (int o = 1; o < 32; o <<= 1) {
        int u = __shfl_up_sync(0xffffffffu, inc, o);
        if (lane >= o) inc += u;
    }
    if (lane == 31) wsm[wid] = inc;
    __syncthreads();
    if (wid == 0) {
        int w = wsm[lane];
        int wi = w;
#pragma unroll
        for (int o = 1; o < 32; o <<= 1) {
            int u = __shfl_up_sync(0xffffffffu, wi, o);
            if (lane >= o) wi += u;
        }
        wsm[lane] = wi - w;
        if (lane == 31) wsm[32] = wi;
    }
    __syncthreads();
    int btotal = wsm[32];

    if (tid == 0) {
        int prefix = 0;
        if (b > 0) {
            while (atomicAdd(&g_sflag[b - 1], 0) == 0) { }
            prefix = g_spfx[b - 1];
        }
        g_spfx[b] = prefix + btotal;
        __threadfence();
        atomicExch(&g_sflag[b], 1);
        s_prefix = prefix;
        if (b == SCAN_BLOCKS - 1) g_off[N_NODES] = prefix + btotal;
    }
    __syncthreads();

    int excl = s_prefix + wsm[wid] + inc - t;
#pragma unroll
    for (int j = 0; j < 4; j++) {
        int g = base + j;
        if (g < N_NODES) { g_off[g] = excl; g_fill[g] = excl; g_cnt[g] = 0; }
        excl += v[j];
    }
}

__global__ void k_fill(const int* __restrict__ src, const int* __restrict__ dst,
                       const float* __restrict__ ew) {
    int t = blockIdx.x * blockDim.x + threadIdx.x;
    int e = t * 4;
    if (e + 3 < N_EDGES) {
        int4   s4 = *(const int4*)&src[e];
        int4   d4 = *(const int4*)&dst[e];
        float4 w4 = *(const float4*)&ew[e];
        int p0 = atomicAdd(&g_fill[d4.x], 1);
        int p1 = atomicAdd(&g_fill[d4.y], 1);
        int p2 = atomicAdd(&g_fill[d4.z], 1);
        int p3 = atomicAdd(&g_fill[d4.w], 1);
        g_edge[p0] = make_int2(s4.x, __float_as_int(w4.x));
        g_edge[p1] = make_int2(s4.y, __float_as_int(w4.y));
        g_edge[p2] = make_int2(s4.z, __float_as_int(w4.z));
        g_edge[p3] = make_int2(s4.w, __float_as_int(w4.w));
    } else {
        for (int i = e; i < N_EDGES; i++) {
            int p = atomicAdd(&g_fill[dst[i]], 1);
            g_edge[p] = make_int2(src[i], __float_as_int(ew[i]));
        }
    }
}

// ---------------- gather (round-6 hot loop) + folded batch dot --------------
__global__ void k_gather(int insel, const int* __restrict__ user,
                         const int* __restrict__ pos, float* __restrict__ out,
                         int first) {
    const float* __restrict__ X = insel ? g_Y : g_X;
    int lane = threadIdx.x & 31;

    if (blockIdx.x >= GB_GATHER) {
        int w = (blockIdx.x - GB_GATHER) * 8 + (threadIdx.x >> 5);
        if (w >= BATCH) return;
        int u  = user[w];
        int it = pos[w];
        float2 a = *(const float2*)&X[(size_t)u * KDIM + lane * 2];
        float2 bb = *(const float2*)&X[((size_t)N_USERS + it) * KDIM + lane * 2];
        float d = a.x * bb.x + a.y * bb.y;
        d += __shfl_xor_sync(0xffffffffu, d, 16);
        d += __shfl_xor_sync(0xffffffffu, d, 8);
        d += __shfl_xor_sync(0xffffffffu, d, 4);
        d += __shfl_xor_sync(0xffffffffu, d, 2);
        d += __shfl_xor_sync(0xffffffffu, d, 1);
        if (lane == 0) out[w] = first ? d : out[w] + d;
        return;
    }

    int n = blockIdx.x * 8 + (threadIdx.x >> 5);
    if (n >= N_NODES) return;
    int b = g_off[n], e = g_off[n + 1];
    float ax = 0.0f, ay = 0.0f, wa = 0.0f;
    int i = b;
    for (; i + 3 < e; i += 4) {
        int2 E0 = g_edge[i];
        int2 E1 = g_edge[i + 1];
        int2 E2 = g_edge[i + 2];
        int2 E3 = g_edge[i + 3];
        float2 v0 = *(const float2*)&X[(size_t)E0.x * KDIM + lane * 2];
        float2 v1 = *(const float2*)&X[(size_t)E1.x * KDIM + lane * 2];
        float2 v2 = *(const float2*)&X[(size_t)E2.x * KDIM + lane * 2];
        float2 v3 = *(const float2*)&X[(size_t)E3.x * KDIM + lane * 2];
        float w0 = __int_as_float(E0.y), w1 = __int_as_float(E1.y);
        float w2 = __int_as_float(E2.y), w3 = __int_as_float(E3.y);
        ax += w0 * v0.x + w1 * v1.x + w2 * v2.x + w3 * v3.x;
        ay += w0 * v0.y + w1 * v1.y + w2 * v2.y + w3 * v3.y;
        wa += w0 + w1 + w2 + w3;
    }
    for (; i < e; i++) {
        int2 E0 = g_edge[i];
        float w0 = __int_as_float(E0.y);
        float2 v0 = *(const float2*)&X[(size_t)E0.x * KDIM + lane * 2];
        ax += w0 * v0.x;
        ay += w0 * v0.y;
        wa += w0;
    }
    *(float2*)&g_S[(size_t)n * KDIM + lane * 2] = make_float2(ax, ay);
    if (insel == 0 && lane == 0) g_wsum[n] = wa;
}

// ---------------- per-layer: GEMM + bias + LeakyReLU + L2-normalize --------
#define ROWP 66
__global__ void __launch_bounds__(128) k_update(
    const float* __restrict__ W1, const float* __restrict__ b1,
    const float* __restrict__ W2, const float* __restrict__ b2,
    int l) {
    __shared__ float sA[64 * ROWP];
    __shared__ float sB[64 * ROWP];
    const float* __restrict__ Xin = (l & 1) ? g_Y : g_X;
    float* __restrict__ Yout      = (l & 1) ? g_X : g_Y;

    int tid = threadIdx.x;
    int grp = tid >> 4;
    int t16 = tid & 15;
    int node0 = blockIdx.x * 64;
    int nb = grp * 8;
    int c = t16 * 4;

    const float* W1l = W1 + l * 4096;
    const float* W2l = W2 + l * 4096;

#pragma unroll
    for (int m = 0; m < 8; m++) {
        int nl = nb + m;
        int n = node0 + nl;
        if (n < N_NODES) {
            float4 sv = *(const float4*)&g_S[(size_t)n * KDIM + c];
            float4 xv = *(const float4*)&Xin[(size_t)n * KDIM + c];
            sA[(c + 0) * ROWP + nl] = sv.x + xv.x;
            sA[(c + 1) * ROWP + nl] = sv.y + xv.y;
            sA[(c + 2) * ROWP + nl] = sv.z + xv.z;
            sA[(c + 3) * ROWP + nl] = sv.w + xv.w;
            sB[(c + 0) * ROWP + nl] = sv.x * xv.x;
            sB[(c + 1) * ROWP + nl] = sv.y * xv.y;
            sB[(c + 2) * ROWP + nl] = sv.z * xv.z;
            sB[(c + 3) * ROWP + nl] = sv.w * xv.w;
        } else {
            sA[(c + 0) * ROWP + nl] = 0.0f;
            sA[(c + 1) * ROWP + nl] = 0.0f;
            sA[(c + 2) * ROWP + nl] = 0.0f;
            sA[(c + 3) * ROWP + nl] = 0.0f;
            sB[(c + 0) * ROWP + nl] = 0.0f;
            sB[(c + 1) * ROWP + nl] = 0.0f;
            sB[(c + 2) * ROWP + nl] = 0.0f;
            sB[(c + 3) * ROWP + nl] = 0.0f;
        }
    }
    __syncwarp();

    float4 B1 = __ldg((const float4*)&b1[l * 64 + c]);
    float4 B2 = __ldg((const float4*)&b2[l * 64 + c]);

    u64 acc[4][4];
#pragma unroll
    for (int p = 0; p < 4; p++) {
        int n0 = node0 + nb + 2 * p;
        float w0 = (n0 < N_NODES) ? g_wsum[n0] : 0.0f;
        float w1 = (n0 + 1 < N_NODES) ? g_wsum[n0 + 1] : 0.0f;
        acc[p][0] = pack2((w0 + 1.0f) * B1.x + w0 * B2.x, (w1 + 1.0f) * B1.x + w1 * B2.x);
        acc[p][1] = pack2((w0 + 1.0f) * B1.y + w0 * B2.y, (w1 + 1.0f) * B1.y + w1 * B2.y);
        acc[p][2] = pack2((w0 + 1.0f) * B1.z + w0 * B2.z, (w1 + 1.0f) * B1.z + w1 * B2.z);
        acc[p][3] = pack2((w0 + 1.0f) * B1.w + w0 * B2.w, (w1 + 1.0f) * B1.w + w1 * B2.w);
    }

#pragma unroll 2
    for (int k = 0; k < 64; k++) {
        float4 w1 = __ldg((const float4*)&W1l[k * 64 + c]);
        float4 w2 = __ldg((const float4*)&W2l[k * 64 + c]);
        u64 d10 = dup2(w1.x), d11 = dup2(w1.y), d12 = dup2(w1.z), d13 = dup2(w1.w);
        u64 d20 = dup2(w2.x), d21 = dup2(w2.y), d22 = dup2(w2.z), d23 = dup2(w2.w);
        const float* ra = &sA[k * ROWP + nb];
        const float* rb = &sB[k * ROWP + nb];
#pragma unroll
        for (int p = 0; p < 4; p++) {
            u64 ap = *(const u64*)&ra[2 * p];
            u64 bp = *(const u64*)&rb[2 * p];
            fma2(acc[p][0], ap, d10);
            fma2(acc[p][1], ap, d11);
            fma2(acc[p][2], ap, d12);
            fma2(acc[p][3], ap, d13);
            fma2(acc[p][0], bp, d20);
            fma2(acc[p][1], bp, d21);
            fma2(acc[p][2], bp, d22);
            fma2(acc[p][3], bp, d23);
        }
    }

#pragma unroll
    for (int p = 0; p < 4; p++) {
        float2 y[4];
#pragma unroll
        for (int j = 0; j < 4; j++) {
            float2 v = unpack2(acc[p][j]);
            y[j].x = v.x > 0.0f ? v.x : NEG_SLOPE * v.x;
            y[j].y = v.y > 0.0f ? v.y : NEG_SLOPE * v.y;
        }
        float ssx = y[0].x * y[0].x + y[1].x * y[1].x + y[2].x * y[2].x + y[3].x * y[3].x;
        float ssy = y[0].y * y[0].y + y[1].y * y[1].y + y[2].y * y[2].y + y[3].y * y[3].y;
#pragma unroll
        for (int o = 1; o < 16; o <<= 1) {
            ssx += __shfl_xor_sync(0xffffffffu, ssx, o);
            ssy += __shfl_xor_sync(0xffffffffu, ssy, o);
        }
        float inv0 = 1.0f / fmaxf(sqrtf(ssx), EPSV);
        float inv1 = 1.0f / fmaxf(sqrtf(ssy), EPSV);
        int n0 = node0 + nb + 2 * p;
        if (n0 < N_NODES)
            *(float4*)&Yout[(size_t)n0 * KDIM + c] =
                make_float4(y[0].x * inv0, y[1].x * inv0, y[2].x * inv0, y[3].x * inv0);
        if (n0 + 1 < N_NODES)
            *(float4*)&Yout[(size_t)(n0 + 1) * KDIM + c] =
                make_float4(y[0].y * inv1, y[1].y * inv1, y[2].y * inv1, y[3].y * inv1);
    }
}

// ---------------- standalone final dot --------------------------------------
__global__ void k_dot(const int* __restrict__ user, const int* __restrict__ pos,
                      float* __restrict__ out, int sel, int first) {
    const float* __restrict__ X = sel ? g_Y : g_X;
    int gthr = blockIdx.x * blockDim.x + threadIdx.x;
    int w = gthr >> 5;
    if (w >= BATCH) return;
    int lane = threadIdx.x & 31;
    int u  = user[w];
    int it = pos[w];
    float2 a = *(const float2*)&X[(size_t)u * KDIM + lane * 2];
    float2 b = *(const float2*)&X[((size_t)N_USERS + it) * KDIM + lane * 2];
    float d = a.x * b.x + a.y * b.y;
    d += __shfl_xor_sync(0xffffffffu, d, 16);
    d += __shfl_xor_sync(0xffffffffu, d, 8);
    d += __shfl_xor_sync(0xffffffffu, d, 4);
    d += __shfl_xor_sync(0xffffffffu, d, 2);
    d += __shfl_xor_sync(0xffffffffu, d, 1);
    if (lane == 0) out[w] = first ? d : out[w] + d;
}

// ---------------- launch ----------------------------------------------------
extern "C" void kernel_launch(void* const* d_in, const int* in_sizes, int n_in,
                              void* d_out, int out_size) {
    const float* Gu   = (const float*)d_in[0];
    const float* Gi   = (const float*)d_in[1];
    const float* W1   = (const float*)d_in[2];
    const float* b1   = (const float*)d_in[3];
    const float* W2   = (const float*)d_in[4];
    const float* b2   = (const float*)d_in[5];
    const float* ew   = (const float*)d_in[6];
    const int*   esrc = (const int*)d_in[7];
    const int*   edst = (const int*)d_in[8];
    const int*   user = (const int*)d_in[9];
    const int*   pos  = (const int*)d_in[10];
    float* out = (float*)d_out;

    const int TB = 256;
    k_init<<<(N_NODES * KDIM / 4 + TB - 1) / TB, TB>>>(Gu, Gi);
    k_hist<<<(N_EDGES / 4 + TB - 1) / TB, TB>>>(edst);
    k_scan37<<<SCAN_BLOCKS, 1024>>>();
    k_fill<<<(N_EDGES / 4 + TB - 1) / TB, TB>>>(esrc, edst, ew);

    for (int l = 0; l < 3; l++) {
        int insel = l & 1;
        k_gather<<<GB_GATHER + DOT_BLOCKS, TB>>>(insel, user, pos, out, l == 0);
        k_update<<<(N_NODES + 63) / 64, 128>>>(W1, b1, W2, b2, l);
    }
    k_dot<<<(BATCH * 32 + TB - 1) / TB, TB>>>(user, pos, out, 1, 0);
}

// round 10
// speedup vs baseline: 1.0509x; 1.0509x over previous
#include <cuda_runtime.h>

#define N_USERS 100000
#define N_ITEMS 50000
#define N_NODES 150000
#define KDIM    64
#define N_EDGES 2000000
#define BATCH   4096
#define NEG_SLOPE 0.01f
#define EPSV    1e-12f

#define SCAN_ELEMS 4096
#define SCAN_BLOCKS ((N_NODES + SCAN_ELEMS - 1) / SCAN_ELEMS)   // 37

typedef unsigned long long u64;

__device__ __forceinline__ u64 dup2(float v) {
    u64 r; asm("mov.b64 %0, {%1, %1};" : "=l"(r) : "f"(v)); return r;
}
__device__ __forceinline__ u64 pack2(float lo, float hi) {
    u64 r; asm("mov.b64 %0, {%1, %2};" : "=l"(r) : "f"(lo), "f"(hi)); return r;
}
__device__ __forceinline__ float2 unpack2(u64 v) {
    float2 f; asm("mov.b64 {%0, %1}, %2;" : "=f"(f.x), "=f"(f.y) : "l"(v)); return f;
}
__device__ __forceinline__ void fma2(u64& d, u64 a, u64 b) {
    asm("fma.rn.f32x2 %0, %1, %2, %0;" : "+l"(d) : "l"(a), "l"(b));
}

// ---------------- scratch ----------------------------------------------------
__device__ float g_X[(size_t)N_NODES * KDIM];
__device__ float g_Y[(size_t)N_NODES * KDIM];
__device__ float g_S[(size_t)N_NODES * KDIM];
__device__ float g_wsum[N_NODES];
__device__ int   g_cnt[N_NODES];
__device__ int   g_off[N_NODES + 1];
__device__ int   g_fill[N_NODES];
__device__ int2  g_edge[N_EDGES];
__device__ int   g_part[SCAN_BLOCKS];
__device__ int   g_partoff[SCAN_BLOCKS];

// ---------------- init: X = concat(Gu, Gi); zero counters ------------------
__global__ void k_init(const float* __restrict__ Gu, const float* __restrict__ Gi) {
    int i = blockIdx.x * blockDim.x + threadIdx.x;
    const int total  = N_NODES * KDIM / 4;
    const int usplit = N_USERS * KDIM / 4;
    if (i < N_NODES) g_cnt[i] = 0;
    if (i >= total) return;
    float4 v = (i < usplit) ? ((const float4*)Gu)[i] : ((const float4*)Gi)[i - usplit];
    ((float4*)g_X)[i] = v;
}

// ---------------- CSR build (8 edges/thread for MLP) ------------------------
__global__ void k_hist(const int* __restrict__ dst) {
    int t = blockIdx.x * blockDim.x + threadIdx.x;
    int e = t * 8;
    if (e + 7 < N_EDGES) {
        int4 a4 = *(const int4*)&dst[e];
        int4 b4 = *(const int4*)&dst[e + 4];
        atomicAdd(&g_cnt[a4.x], 1);
        atomicAdd(&g_cnt[a4.y], 1);
        atomicAdd(&g_cnt[a4.z], 1);
        atomicAdd(&g_cnt[a4.w], 1);
        atomicAdd(&g_cnt[b4.x], 1);
        atomicAdd(&g_cnt[b4.y], 1);
        atomicAdd(&g_cnt[b4.z], 1);
        atomicAdd(&g_cnt[b4.w], 1);
    } else {
        for (int i = e; i < N_EDGES; i++) atomicAdd(&g_cnt[dst[i]], 1);
    }
}

__global__ void __launch_bounds__(1024) k_part() {
    __shared__ int red[32];
    int tid = threadIdx.x;
    int base = blockIdx.x * SCAN_ELEMS + tid * 4;
    int s = 0;
#pragma unroll
    for (int j = 0; j < 4; j++) {
        int g = base + j;
        s += (g < N_NODES) ? g_cnt[g] : 0;
    }
#pragma unroll
    for (int o = 16; o; o >>= 1) s += __shfl_xor_sync(0xffffffffu, s, o);
    if ((tid & 31) == 0) red[tid >> 5] = s;
    __syncthreads();
    if (tid < 32) {
        int v = red[tid];
#pragma unroll
        for (int o = 16; o; o >>= 1) v += __shfl_xor_sync(0xffffffffu, v, o);
        if (tid == 0) g_part[blockIdx.x] = v;
    }
}

__global__ void k_scanpart() {
    __shared__ int s[64];
    int tid = threadIdx.x;
    int v = (tid < SCAN_BLOCKS) ? g_part[tid] : 0;
    s[tid] = v;
    __syncthreads();
#pragma unroll
    for (int o = 1; o < 64; o <<= 1) {
        int t = (tid >= o) ? s[tid - o] : 0;
        __syncthreads();
        s[tid] += t;
        __syncthreads();
    }
    if (tid < SCAN_BLOCKS) g_partoff[tid] = s[tid] - v;
    if (tid == 63) g_off[N_NODES] = s[63];
}

__global__ void __launch_bounds__(1024) k_scanfinal() {
    __shared__ int wsm[33];
    int tid = threadIdx.x;
    int lane = tid & 31, wid = tid >> 5;
    int base = blockIdx.x * SCAN_ELEMS + tid * 4;
    int v[4];
    int t = 0;
#pragma unroll
    for (int j = 0; j < 4; j++) {
        int g = base + j;
        v[j] = (g < N_NODES) ? g_cnt[g] : 0;
        t += v[j];
    }
    int inc = t;
#pragma unroll
    for (int o = 1; o < 32; o <<= 1) {
        int u = __shfl_up_sync(0xffffffffu, inc, o);
        if (lane >= o) inc += u;
    }
    if (lane == 31) wsm[wid] = inc;
    __syncthreads();
    if (wid == 0) {
        int w = wsm[lane];
        int wi = w;
#pragma unroll
        for (int o = 1; o < 32; o <<= 1) {
            int u = __shfl_up_sync(0xffffffffu, wi, o);
            if (lane >= o) wi += u;
        }
        wsm[lane] = wi - w;
    }
    __syncthreads();
    int excl = g_partoff[blockIdx.x] + wsm[wid] + inc - t;
#pragma unroll
    for (int j = 0; j < 4; j++) {
        int g = base + j;
        if (g < N_NODES) { g_off[g] = excl; g_fill[g] = excl; }
        excl += v[j];
    }
}

__global__ void k_fill(const int* __restrict__ src, const int* __restrict__ dst,
                       const float* __restrict__ ew) {
    int t = blockIdx.x * blockDim.x + threadIdx.x;
    int e = t * 8;
    if (e + 7 < N_EDGES) {
        int4   sa = *(const int4*)&src[e];
        int4   sb = *(const int4*)&src[e + 4];
        int4   da = *(const int4*)&dst[e];
        int4   db = *(const int4*)&dst[e + 4];
        float4 wa = *(const float4*)&ew[e];
        float4 wb = *(const float4*)&ew[e + 4];
        int p0 = atomicAdd(&g_fill[da.x], 1);
        int p1 = atomicAdd(&g_fill[da.y], 1);
        int p2 = atomicAdd(&g_fill[da.z], 1);
        int p3 = atomicAdd(&g_fill[da.w], 1);
        int p4 = atomicAdd(&g_fill[db.x], 1);
        int p5 = atomicAdd(&g_fill[db.y], 1);
        int p6 = atomicAdd(&g_fill[db.z], 1);
        int p7 = atomicAdd(&g_fill[db.w], 1);
        g_edge[p0] = make_int2(sa.x, __float_as_int(wa.x));
        g_edge[p1] = make_int2(sa.y, __float_as_int(wa.y));
        g_edge[p2] = make_int2(sa.z, __float_as_int(wa.z));
        g_edge[p3] = make_int2(sa.w, __float_as_int(wa.w));
        g_edge[p4] = make_int2(sb.x, __float_as_int(wb.x));
        g_edge[p5] = make_int2(sb.y, __float_as_int(wb.y));
        g_edge[p6] = make_int2(sb.z, __float_as_int(wb.z));
        g_edge[p7] = make_int2(sb.w, __float_as_int(wb.w));
    } else {
        for (int i = e; i < N_EDGES; i++) {
            int p = atomicAdd(&g_fill[dst[i]], 1);
            g_edge[p] = make_int2(src[i], __float_as_int(ew[i]));
        }
    }
}

// ---------------- per-layer: S[n] = sum_e w_e * x[src_e]; wsum[n] = sum w --
__global__ void k_gather(int insel) {
    const float* __restrict__ X = insel ? g_Y : g_X;
    int gthr = blockIdx.x * blockDim.x + threadIdx.x;
    int n = gthr >> 5;
    if (n >= N_NODES) return;
    int lane = threadIdx.x & 31;
    int b = g_off[n], e = g_off[n + 1];
    float ax = 0.0f, ay = 0.0f, wa = 0.0f;
    int i = b;
    for (; i + 3 < e; i += 4) {
        int2 E0 = g_edge[i];
        int2 E1 = g_edge[i + 1];
        int2 E2 = g_edge[i + 2];
        int2 E3 = g_edge[i + 3];
        float2 v0 = *(const float2*)&X[(size_t)E0.x * KDIM + lane * 2];
        float2 v1 = *(const float2*)&X[(size_t)E1.x * KDIM + lane * 2];
        float2 v2 = *(const float2*)&X[(size_t)E2.x * KDIM + lane * 2];
        float2 v3 = *(const float2*)&X[(size_t)E3.x * KDIM + lane * 2];
        float w0 = __int_as_float(E0.y), w1 = __int_as_float(E1.y);
        float w2 = __int_as_float(E2.y), w3 = __int_as_float(E3.y);
        ax += w0 * v0.x + w1 * v1.x + w2 * v2.x + w3 * v3.x;
        ay += w0 * v0.y + w1 * v1.y + w2 * v2.y + w3 * v3.y;
        wa += w0 + w1 + w2 + w3;
    }
    for (; i < e; i++) {
        int2 E0 = g_edge[i];
        float w0 = __int_as_float(E0.y);
        float2 v0 = *(const float2*)&X[(size_t)E0.x * KDIM + lane * 2];
        ax += w0 * v0.x;
        ay += w0 * v0.y;
        wa += w0;
    }
    *(float2*)&g_S[(size_t)n * KDIM + lane * 2] = make_float2(ax, ay);
    if (insel == 0 && lane == 0) g_wsum[n] = wa;
}

// ---------------- per-layer: GEMM + bias + LeakyReLU + L2-normalize --------
#define ROWP 66
__global__ void __launch_bounds__(128) k_update(
    const float* __restrict__ W1, const float* __restrict__ b1,
    const float* __restrict__ W2, const float* __restrict__ b2,
    int l) {
    __shared__ float sA[64 * ROWP];
    __shared__ float sB[64 * ROWP];
    const float* __restrict__ Xin = (l & 1) ? g_Y : g_X;
    float* __restrict__ Yout      = (l & 1) ? g_X : g_Y;

    int tid = threadIdx.x;
    int grp = tid >> 4;
    int t16 = tid & 15;
    int node0 = blockIdx.x * 64;
    int nb = grp * 8;
    int c = t16 * 4;

    const float* W1l = W1 + l * 4096;
    const float* W2l = W2 + l * 4096;

#pragma unroll
    for (int m = 0; m < 8; m++) {
        int nl = nb + m;
        int n = node0 + nl;
        if (n < N_NODES) {
            float4 sv = *(const float4*)&g_S[(size_t)n * KDIM + c];
            float4 xv = *(const float4*)&Xin[(size_t)n * KDIM + c];
            sA[(c + 0) * ROWP + nl] = sv.x + xv.x;
            sA[(c + 1) * ROWP + nl] = sv.y + xv.y;
            sA[(c + 2) * ROWP + nl] = sv.z + xv.z;
            sA[(c + 3) * ROWP + nl] = sv.w + xv.w;
            sB[(c + 0) * ROWP + nl] = sv.x * xv.x;
            sB[(c + 1) * ROWP + nl] = sv.y * xv.y;
            sB[(c + 2) * ROWP + nl] = sv.z * xv.z;
            sB[(c + 3) * ROWP + nl] = sv.w * xv.w;
        } else {
            sA[(c + 0) * ROWP + nl] = 0.0f;
            sA[(c + 1) * ROWP + nl] = 0.0f;
            sA[(c + 2) * ROWP + nl] = 0.0f;
            sA[(c + 3) * ROWP + nl] = 0.0f;
            sB[(c + 0) * ROWP + nl] = 0.0f;
            sB[(c + 1) * ROWP + nl] = 0.0f;
            sB[(c + 2) * ROWP + nl] = 0.0f;
            sB[(c + 3) * ROWP + nl] = 0.0f;
        }
    }
    __syncwarp();

    float4 B1 = __ldg((const float4*)&b1[l * 64 + c]);
    float4 B2 = __ldg((const float4*)&b2[l * 64 + c]);

    u64 acc[4][4];
#pragma unroll
    for (int p = 0; p < 4; p++) {
        int n0 = node0 + nb + 2 * p;
        float w0 = (n0 < N_NODES) ? g_wsum[n0] : 0.0f;
        float w1 = (n0 + 1 < N_NODES) ? g_wsum[n0 + 1] : 0.0f;
        acc[p][0] = pack2((w0 + 1.0f) * B1.x + w0 * B2.x, (w1 + 1.0f) * B1.x + w1 * B2.x);
        acc[p][1] = pack2((w0 + 1.0f) * B1.y + w0 * B2.y, (w1 + 1.0f) * B1.y + w1 * B2.y);
        acc[p][2] = pack2((w0 + 1.0f) * B1.z + w0 * B2.z, (w1 + 1.0f) * B1.z + w1 * B2.z);
        acc[p][3] = pack2((w0 + 1.0f) * B1.w + w0 * B2.w, (w1 + 1.0f) * B1.w + w1 * B2.w);
    }

#pragma unroll 2
    for (int k = 0; k < 64; k++) {
        float4 w1 = __ldg((const float4*)&W1l[k * 64 + c]);
        float4 w2 = __ldg((const float4*)&W2l[k * 64 + c]);
        u64 d10 = dup2(w1.x), d11 = dup2(w1.y), d12 = dup2(w1.z), d13 = dup2(w1.w);
        u64 d20 = dup2(w2.x), d21 = dup2(w2.y), d22 = dup2(w2.z), d23 = dup2(w2.w);
        const float* ra = &sA[k * ROWP + nb];
        const float* rb = &sB[k * ROWP + nb];
#pragma unroll
        for (int p = 0; p < 4; p++) {
            u64 ap = *(const u64*)&ra[2 * p];
            u64 bp = *(const u64*)&rb[2 * p];
            fma2(acc[p][0], ap, d10);
            fma2(acc[p][1], ap, d11);
            fma2(acc[p][2], ap, d12);
            fma2(acc[p][3], ap, d13);
            fma2(acc[p][0], bp, d20);
            fma2(acc[p][1], bp, d21);
            fma2(acc[p][2], bp, d22);
            fma2(acc[p][3], bp, d23);
        }
    }

#pragma unroll
    for (int p = 0; p < 4; p++) {
        float2 y[4];
#pragma unroll
        for (int j = 0; j < 4; j++) {
            float2 v = unpack2(acc[p][j]);
            y[j].x = v.x > 0.0f ? v.x : NEG_SLOPE * v.x;
            y[j].y = v.y > 0.0f ? v.y : NEG_SLOPE * v.y;
        }
        float ssx = y[0].x * y[0].x + y[1].x * y[1].x + y[2].x * y[2].x + y[3].x * y[3].x;
        float ssy = y[0].y * y[0].y + y[1].y * y[1].y + y[2].y * y[2].y + y[3].y * y[3].y;
#pragma unroll
        for (int o = 1; o < 16; o <<= 1) {
            ssx += __shfl_xor_sync(0xffffffffu, ssx, o);
            ssy += __shfl_xor_sync(0xffffffffu, ssy, o);
        }
        float inv0 = 1.0f / fmaxf(sqrtf(ssx), EPSV);
        float inv1 = 1.0f / fmaxf(sqrtf(ssy), EPSV);
        int n0 = node0 + nb + 2 * p;
        if (n0 < N_NODES)
            *(float4*)&Yout[(size_t)n0 * KDIM + c] =
                make_float4(y[0].x * inv0, y[1].x * inv0, y[2].x * inv0, y[3].x * inv0);
        if (n0 + 1 < N_NODES)
            *(float4*)&Yout[(size_t)(n0 + 1) * KDIM + c] =
                make_float4(y[0].y * inv1, y[1].y * inv1, y[2].y * inv1, y[3].y * inv1);
    }
}

// ---------------- incremental batch dot ------------------------------------
__global__ void k_dot(const int* __restrict__ user, const int* __restrict__ pos,
                      float* __restrict__ out, int sel, int first) {
    const float* __restrict__ X = sel ? g_Y : g_X;
    int gthr = blockIdx.x * blockDim.x + threadIdx.x;
    int w = gthr >> 5;
    if (w >= BATCH) return;
    int lane = threadIdx.x & 31;
    int u  = user[w];
    int it = pos[w];
    float2 a = *(const float2*)&X[(size_t)u * KDIM + lane * 2];
    float2 b = *(const float2*)&X[((size_t)N_USERS + it) * KDIM + lane * 2];
    float d = a.x * b.x + a.y * b.y;
    d += __shfl_xor_sync(0xffffffffu, d, 16);
    d += __shfl_xor_sync(0xffffffffu, d, 8);
    d += __shfl_xor_sync(0xffffffffu, d, 4);
    d += __shfl_xor_sync(0xffffffffu, d, 2);
    d += __shfl_xor_sync(0xffffffffu, d, 1);
    if (lane == 0) out[w] = first ? d : out[w] + d;
}

// ---------------- launch ----------------------------------------------------
extern "C" void kernel_launch(void* const* d_in, const int* in_sizes, int n_in,
                              void* d_out, int out_size) {
    const float* Gu   = (const float*)d_in[0];
    const float* Gi   = (const float*)d_in[1];
    const float* W1   = (const float*)d_in[2];
    const float* b1   = (const float*)d_in[3];
    const float* W2   = (const float*)d_in[4];
    const float* b2   = (const float*)d_in[5];
    const float* ew   = (const float*)d_in[6];
    const int*   esrc = (const int*)d_in[7];
    const int*   edst = (const int*)d_in[8];
    const int*   user = (const int*)d_in[9];
    const int*   pos  = (const int*)d_in[10];
    float* out = (float*)d_out;

    const int TB = 256;
    k_init<<<(N_NODES * KDIM / 4 + TB - 1) / TB, TB>>>(Gu, Gi);
    k_hist<<<(N_EDGES / 8 + TB - 1) / TB, TB>>>(edst);
    k_part<<<SCAN_BLOCKS, 1024>>>();
    k_scanpart<<<1, 64>>>();
    k_scanfinal<<<SCAN_BLOCKS, 1024>>>();
    k_fill<<<(N_EDGES / 8 + TB - 1) / TB, TB>>>(esrc, edst, ew);

    k_dot<<<(BATCH * 32 + TB - 1) / TB, TB>>>(user, pos, out, /*sel=*/0, /*first=*/1);

    for (int l = 0; l < 3; l++) {
        int insel  = l & 1;
        int outsel = insel ^ 1;
        k_gather<<<(N_NODES * 32 + TB - 1) / TB, TB>>>(insel);
        k_update<<<(N_NODES + 63) / 64, 128>>>(W1, b1, W2, b2, l);
        k_dot<<<(BATCH * 32 + TB - 1) / TB, TB>>>(user, pos, out, outsel, /*first=*/0);
    }
}

// round 11
// speedup vs baseline: 1.1192x; 1.0650x over previous
#include <cuda_runtime.h>
#include <cuda_fp16.h>

#define N_USERS 100000
#define N_ITEMS 50000
#define N_NODES 150000
#define KDIM    64
#define N_EDGES 2000000
#define BATCH   4096
#define NEG_SLOPE 0.01f
#define EPSV    1e-12f

#define SCAN_ELEMS 4096
#define SCAN_BLOCKS ((N_NODES + SCAN_ELEMS - 1) / SCAN_ELEMS)   // 37

typedef unsigned long long u64;

__device__ __forceinline__ u64 dup2(float v) {
    u64 r; asm("mov.b64 %0, {%1, %1};" : "=l"(r) : "f"(v)); return r;
}
__device__ __forceinline__ u64 pack2(float lo, float hi) {
    u64 r; asm("mov.b64 %0, {%1, %2};" : "=l"(r) : "f"(lo), "f"(hi)); return r;
}
__device__ __forceinline__ float2 unpack2(u64 v) {
    float2 f; asm("mov.b64 {%0, %1}, %2;" : "=f"(f.x), "=f"(f.y) : "l"(v)); return f;
}
__device__ __forceinline__ void fma2(u64& d, u64 a, u64 b) {
    asm("fma.rn.f32x2 %0, %1, %2, %0;" : "+l"(d) : "l"(a), "l"(b));
}

// ---------------- scratch ----------------------------------------------------
__device__ float   g_X[(size_t)N_NODES * KDIM];
__device__ float   g_Y[(size_t)N_NODES * KDIM];
__device__ __half2 g_Xh[(size_t)N_NODES * KDIM / 2];   // fp16 mirror of g_X
__device__ __half2 g_Yh[(size_t)N_NODES * KDIM / 2];   // fp16 mirror of g_Y
__device__ float   g_S[(size_t)N_NODES * KDIM];
__device__ float   g_wsum[N_NODES];
__device__ int     g_cnt[N_NODES];
__device__ int     g_off[N_NODES + 1];
__device__ int     g_fill[N_NODES];
__device__ int2    g_edge[N_EDGES];
__device__ int     g_part[SCAN_BLOCKS];
__device__ int     g_partoff[SCAN_BLOCKS];

// ---------------- init: X = concat(Gu, Gi) + fp16 mirror; zero counters -----
__global__ void k_init(const float* __restrict__ Gu, const float* __restrict__ Gi) {
    int i = blockIdx.x * blockDim.x + threadIdx.x;
    const int total  = N_NODES * KDIM / 4;
    const int usplit = N_USERS * KDIM / 4;
    if (i < N_NODES) g_cnt[i] = 0;
    if (i >= total) return;
    float4 v = (i < usplit) ? ((const float4*)Gu)[i] : ((const float4*)Gi)[i - usplit];
    ((float4*)g_X)[i] = v;
    __half2 h0 = __floats2half2_rn(v.x, v.y);
    __half2 h1 = __floats2half2_rn(v.z, v.w);
    g_Xh[i * 2]     = h0;
    g_Xh[i * 2 + 1] = h1;
}

// ---------------- CSR build --------------------------------------------------
__global__ void k_hist(const int* __restrict__ dst) {
    int t = blockIdx.x * blockDim.x + threadIdx.x;
    int e = t * 8;
    if (e + 7 < N_EDGES) {
        int4 a4 = *(const int4*)&dst[e];
        int4 b4 = *(const int4*)&dst[e + 4];
        atomicAdd(&g_cnt[a4.x], 1);
        atomicAdd(&g_cnt[a4.y], 1);
        atomicAdd(&g_cnt[a4.z], 1);
        atomicAdd(&g_cnt[a4.w], 1);
        atomicAdd(&g_cnt[b4.x], 1);
        atomicAdd(&g_cnt[b4.y], 1);
        atomicAdd(&g_cnt[b4.z], 1);
        atomicAdd(&g_cnt[b4.w], 1);
    } else {
        for (int i = e; i < N_EDGES; i++) atomicAdd(&g_cnt[dst[i]], 1);
    }
}

__global__ void __launch_bounds__(1024) k_part() {
    __shared__ int red[32];
    int tid = threadIdx.x;
    int base = blockIdx.x * SCAN_ELEMS + tid * 4;
    int s = 0;
#pragma unroll
    for (int j = 0; j < 4; j++) {
        int g = base + j;
        s += (g < N_NODES) ? g_cnt[g] : 0;
    }
#pragma unroll
    for (int o = 16; o; o >>= 1) s += __shfl_xor_sync(0xffffffffu, s, o);
    if ((tid & 31) == 0) red[tid >> 5] = s;
    __syncthreads();
    if (tid < 32) {
        int v = red[tid];
#pragma unroll
        for (int o = 16; o; o >>= 1) v += __shfl_xor_sync(0xffffffffu, v, o);
        if (tid == 0) g_part[blockIdx.x] = v;
    }
}

__global__ void k_scanpart() {
    __shared__ int s[64];
    int tid = threadIdx.x;
    int v = (tid < SCAN_BLOCKS) ? g_part[tid] : 0;
    s[tid] = v;
    __syncthreads();
#pragma unroll
    for (int o = 1; o < 64; o <<= 1) {
        int t = (tid >= o) ? s[tid - o] : 0;
        __syncthreads();
        s[tid] += t;
        __syncthreads();
    }
    if (tid < SCAN_BLOCKS) g_partoff[tid] = s[tid] - v;
    if (tid == 63) g_off[N_NODES] = s[63];
}

__global__ void __launch_bounds__(1024) k_scanfinal() {
    __shared__ int wsm[33];
    int tid = threadIdx.x;
    int lane = tid & 31, wid = tid >> 5;
    int base = blockIdx.x * SCAN_ELEMS + tid * 4;
    int v[4];
    int t = 0;
#pragma unroll
    for (int j = 0; j < 4; j++) {
        int g = base + j;
        v[j] = (g < N_NODES) ? g_cnt[g] : 0;
        t += v[j];
    }
    int inc = t;
#pragma unroll
    for (int o = 1; o < 32; o <<= 1) {
        int u = __shfl_up_sync(0xffffffffu, inc, o);
        if (lane >= o) inc += u;
    }
    if (lane == 31) wsm[wid] = inc;
    __syncthreads();
    if (wid == 0) {
        int w = wsm[lane];
        int wi = w;
#pragma unroll
        for (int o = 1; o < 32; o <<= 1) {
            int u = __shfl_up_sync(0xffffffffu, wi, o);
            if (lane >= o) wi += u;
        }
        wsm[lane] = wi - w;
    }
    __syncthreads();
    int excl = g_partoff[blockIdx.x] + wsm[wid] + inc - t;
#pragma unroll
    for (int j = 0; j < 4; j++) {
        int g = base + j;
        if (g < N_NODES) { g_off[g] = excl; g_fill[g] = excl; }
        excl += v[j];
    }
}

__global__ void k_fill(const int* __restrict__ src, const int* __restrict__ dst,
                       const float* __restrict__ ew) {
    int t = blockIdx.x * blockDim.x + threadIdx.x;
    int e = t * 8;
    if (e + 7 < N_EDGES) {
        int4   sa = *(const int4*)&src[e];
        int4   sb = *(const int4*)&src[e + 4];
        int4   da = *(const int4*)&dst[e];
        int4   db = *(const int4*)&dst[e + 4];
        float4 wa = *(const float4*)&ew[e];
        float4 wb = *(const float4*)&ew[e + 4];
        int p0 = atomicAdd(&g_fill[da.x], 1);
        int p1 = atomicAdd(&g_fill[da.y], 1);
        int p2 = atomicAdd(&g_fill[da.z], 1);
        int p3 = atomicAdd(&g_fill[da.w], 1);
        int p4 = atomicAdd(&g_fill[db.x], 1);
        int p5 = atomicAdd(&g_fill[db.y], 1);
        int p6 = atomicAdd(&g_fill[db.z], 1);
        int p7 = atomicAdd(&g_fill[db.w], 1);
        g_edge[p0] = make_int2(sa.x, __float_as_int(wa.x));
        g_edge[p1] = make_int2(sa.y, __float_as_int(wa.y));
        g_edge[p2] = make_int2(sa.z, __float_as_int(wa.z));
        g_edge[p3] = make_int2(sa.w, __float_as_int(wa.w));
        g_edge[p4] = make_int2(sb.x, __float_as_int(wb.x));
        g_edge[p5] = make_int2(sb.y, __float_as_int(wb.y));
        g_edge[p6] = make_int2(sb.z, __float_as_int(wb.z));
        g_edge[p7] = make_int2(sb.w, __float_as_int(wb.w));
    } else {
        for (int i = e; i < N_EDGES; i++) {
            int p = atomicAdd(&g_fill[dst[i]], 1);
            g_edge[p] = make_int2(src[i], __float_as_int(ew[i]));
        }
    }
}

// ---------------- per-layer gather over fp16 mirror --------------------------
// 1 warp/node; each lane owns 2 columns (one half2 = 4B); full row = 128B = 1 line.
__global__ void k_gather(int insel) {
    const __half2* __restrict__ X = insel ? g_Yh : g_Xh;
    int gthr = blockIdx.x * blockDim.x + threadIdx.x;
    int n = gthr >> 5;
    if (n >= N_NODES) return;
    int lane = threadIdx.x & 31;
    int b = g_off[n], e = g_off[n + 1];
    float ax = 0.0f, ay = 0.0f, wa = 0.0f;
    int i = b;
    for (; i + 3 < e; i += 4) {
        int2 E0 = g_edge[i];
        int2 E1 = g_edge[i + 1];
        int2 E2 = g_edge[i + 2];
        int2 E3 = g_edge[i + 3];
        float2 v0 = __half22float2(X[(size_t)E0.x * 32 + lane]);
        float2 v1 = __half22float2(X[(size_t)E1.x * 32 + lane]);
        float2 v2 = __half22float2(X[(size_t)E2.x * 32 + lane]);
        float2 v3 = __half22float2(X[(size_t)E3.x * 32 + lane]);
        float w0 = __int_as_float(E0.y), w1 = __int_as_float(E1.y);
        float w2 = __int_as_float(E2.y), w3 = __int_as_float(E3.y);
        ax += w0 * v0.x + w1 * v1.x + w2 * v2.x + w3 * v3.x;
        ay += w0 * v0.y + w1 * v1.y + w2 * v2.y + w3 * v3.y;
        wa += w0 + w1 + w2 + w3;
    }
    for (; i < e; i++) {
        int2 E0 = g_edge[i];
        float w0 = __int_as_float(E0.y);
        float2 v0 = __half22float2(X[(size_t)E0.x * 32 + lane]);
        ax += w0 * v0.x;
        ay += w0 * v0.y;
        wa += w0;
    }
    *(float2*)&g_S[(size_t)n * KDIM + lane * 2] = make_float2(ax, ay);
    if (insel == 0 && lane == 0) g_wsum[n] = wa;
}

// ---------------- per-layer: GEMM + bias + LeakyReLU + L2-normalize ---------
#define ROWP 66
__global__ void __launch_bounds__(128) k_update(
    const float* __restrict__ W1, const float* __restrict__ b1,
    const float* __restrict__ W2, const float* __restrict__ b2,
    int l) {
    __shared__ float sA[64 * ROWP];
    __shared__ float sB[64 * ROWP];
    const float* __restrict__ Xin = (l & 1) ? g_Y : g_X;
    float* __restrict__ Yout      = (l & 1) ? g_X : g_Y;
    __half2* __restrict__ Yh      = (l & 1) ? g_Xh : g_Yh;

    int tid = threadIdx.x;
    int grp = tid >> 4;
    int t16 = tid & 15;
    int node0 = blockIdx.x * 64;
    int nb = grp * 8;
    int c = t16 * 4;

    const float* W1l = W1 + l * 4096;
    const float* W2l = W2 + l * 4096;

#pragma unroll
    for (int m = 0; m < 8; m++) {
        int nl = nb + m;
        int n = node0 + nl;
        if (n < N_NODES) {
            float4 sv = *(const float4*)&g_S[(size_t)n * KDIM + c];
            float4 xv = *(const float4*)&Xin[(size_t)n * KDIM + c];
            sA[(c + 0) * ROWP + nl] = sv.x + xv.x;
            sA[(c + 1) * ROWP + nl] = sv.y + xv.y;
            sA[(c + 2) * ROWP + nl] = sv.z + xv.z;
            sA[(c + 3) * ROWP + nl] = sv.w + xv.w;
            sB[(c + 0) * ROWP + nl] = sv.x * xv.x;
            sB[(c + 1) * ROWP + nl] = sv.y * xv.y;
            sB[(c + 2) * ROWP + nl] = sv.z * xv.z;
            sB[(c + 3) * ROWP + nl] = sv.w * xv.w;
        } else {
            sA[(c + 0) * ROWP + nl] = 0.0f;
            sA[(c + 1) * ROWP + nl] = 0.0f;
            sA[(c + 2) * ROWP + nl] = 0.0f;
            sA[(c + 3) * ROWP + nl] = 0.0f;
            sB[(c + 0) * ROWP + nl] = 0.0f;
            sB[(c + 1) * ROWP + nl] = 0.0f;
            sB[(c + 2) * ROWP + nl] = 0.0f;
            sB[(c + 3) * ROWP + nl] = 0.0f;
        }
    }
    __syncwarp();

    float4 B1 = __ldg((const float4*)&b1[l * 64 + c]);
    float4 B2 = __ldg((const float4*)&b2[l * 64 + c]);

    u64 acc[4][4];
#pragma unroll
    for (int p = 0; p < 4; p++) {
        int n0 = node0 + nb + 2 * p;
        float w0 = (n0 < N_NODES) ? g_wsum[n0] : 0.0f;
        float w1 = (n0 + 1 < N_NODES) ? g_wsum[n0 + 1] : 0.0f;
        acc[p][0] = pack2((w0 + 1.0f) * B1.x + w0 * B2.x, (w1 + 1.0f) * B1.x + w1 * B2.x);
        acc[p][1] = pack2((w0 + 1.0f) * B1.y + w0 * B2.y, (w1 + 1.0f) * B1.y + w1 * B2.y);
        acc[p][2] = pack2((w0 + 1.0f) * B1.z + w0 * B2.z, (w1 + 1.0f) * B1.z + w1 * B2.z);
        acc[p][3] = pack2((w0 + 1.0f) * B1.w + w0 * B2.w, (w1 + 1.0f) * B1.w + w1 * B2.w);
    }

#pragma unroll 2
    for (int k = 0; k < 64; k++) {
        float4 w1 = __ldg((const float4*)&W1l[k * 64 + c]);
        float4 w2 = __ldg((const float4*)&W2l[k * 64 + c]);
        u64 d10 = dup2(w1.x), d11 = dup2(w1.y), d12 = dup2(w1.z), d13 = dup2(w1.w);
        u64 d20 = dup2(w2.x), d21 = dup2(w2.y), d22 = dup2(w2.z), d23 = dup2(w2.w);
        const float* ra = &sA[k * ROWP + nb];
        const float* rb = &sB[k * ROWP + nb];
#pragma unroll
        for (int p = 0; p < 4; p++) {
            u64 ap = *(const u64*)&ra[2 * p];
            u64 bp = *(const u64*)&rb[2 * p];
            fma2(acc[p][0], ap, d10);
            fma2(acc[p][1], ap, d11);
            fma2(acc[p][2], ap, d12);
            fma2(acc[p][3], ap, d13);
            fma2(acc[p][0], bp, d20);
            fma2(acc[p][1], bp, d21);
            fma2(acc[p][2], bp, d22);
            fma2(acc[p][3], bp, d23);
        }
    }

#pragma unroll
    for (int p = 0; p < 4; p++) {
        float2 y[4];
#pragma unroll
        for (int j = 0; j < 4; j++) {
            float2 v = unpack2(acc[p][j]);
            y[j].x = v.x > 0.0f ? v.x : NEG_SLOPE * v.x;
            y[j].y = v.y > 0.0f ? v.y : NEG_SLOPE * v.y;
        }
        float ssx = y[0].x * y[0].x + y[1].x * y[1].x + y[2].x * y[2].x + y[3].x * y[3].x;
        float ssy = y[0].y * y[0].y + y[1].y * y[1].y + y[2].y * y[2].y + y[3].y * y[3].y;
#pragma unroll
        for (int o = 1; o < 16; o <<= 1) {
            ssx += __shfl_xor_sync(0xffffffffu, ssx, o);
            ssy += __shfl_xor_sync(0xffffffffu, ssy, o);
        }
        float inv0 = 1.0f / fmaxf(sqrtf(ssx), EPSV);
        float inv1 = 1.0f / fmaxf(sqrtf(ssy), EPSV);
        int n0 = node0 + nb + 2 * p;
        if (n0 < N_NODES) {
            float4 o0 = make_float4(y[0].x * inv0, y[1].x * inv0, y[2].x * inv0, y[3].x * inv0);
            *(float4*)&Yout[(size_t)n0 * KDIM + c] = o0;
            Yh[(size_t)n0 * 32 + (c >> 1)]     = __floats2half2_rn(o0.x, o0.y);
            Yh[(size_t)n0 * 32 + (c >> 1) + 1] = __floats2half2_rn(o0.z, o0.w);
        }
        if (n0 + 1 < N_NODES) {
            float4 o1 = make_float4(y[0].y * inv1, y[1].y * inv1, y[2].y * inv1, y[3].y * inv1);
            *(float4*)&Yout[(size_t)(n0 + 1) * KDIM + c] = o1;
            Yh[(size_t)(n0 + 1) * 32 + (c >> 1)]     = __floats2half2_rn(o1.x, o1.y);
            Yh[(size_t)(n0 + 1) * 32 + (c >> 1) + 1] = __floats2half2_rn(o1.z, o1.w);
        }
    }
}

// ---------------- incremental batch dot (fp32 buffers) -----------------------
__global__ void k_dot(const int* __restrict__ user, const int* __restrict__ pos,
                      float* __restrict__ out, int sel, int first) {
    const float* __restrict__ X = sel ? g_Y : g_X;
    int gthr = blockIdx.x * blockDim.x + threadIdx.x;
    int w = gthr >> 5;
    if (w >= BATCH) return;
    int lane = threadIdx.x & 31;
    int u  = user[w];
    int it = pos[w];
    float2 a = *(const float2*)&X[(size_t)u * KDIM + lane * 2];
    float2 b = *(const float2*)&X[((size_t)N_USERS + it) * KDIM + lane * 2];
    float d = a.x * b.x + a.y * b.y;
    d += __shfl_xor_sync(0xffffffffu, d, 16);
    d += __shfl_xor_sync(0xffffffffu, d, 8);
    d += __shfl_xor_sync(0xffffffffu, d, 4);
    d += __shfl_xor_sync(0xffffffffu, d, 2);
    d += __shfl_xor_sync(0xffffffffu, d, 1);
    if (lane == 0) out[w] = first ? d : out[w] + d;
}

// ---------------- launch ------------------------------------------------------
extern "C" void kernel_launch(void* const* d_in, const int* in_sizes, int n_in,
                              void* d_out, int out_size) {
    const float* Gu   = (const float*)d_in[0];
    const float* Gi   = (const float*)d_in[1];
    const float* W1   = (const float*)d_in[2];
    const float* b1   = (const float*)d_in[3];
    const float* W2   = (const float*)d_in[4];
    const float* b2   = (const float*)d_in[5];
    const float* ew   = (const float*)d_in[6];
    const int*   esrc = (const int*)d_in[7];
    const int*   edst = (const int*)d_in[8];
    const int*   user = (const int*)d_in[9];
    const int*   pos  = (const int*)d_in[10];
    float* out = (float*)d_out;

    const int TB = 256;
    k_init<<<(N_NODES * KDIM / 4 + TB - 1) / TB, TB>>>(Gu, Gi);
    k_hist<<<(N_EDGES / 8 + TB - 1) / TB, TB>>>(edst);
    k_part<<<SCAN_BLOCKS, 1024>>>();
    k_scanpart<<<1, 64>>>();
    k_scanfinal<<<SCAN_BLOCKS, 1024>>>();
    k_fill<<<(N_EDGES / 8 + TB - 1) / TB, TB>>>(esrc, edst, ew);

    k_dot<<<(BATCH * 32 + TB - 1) / TB, TB>>>(user, pos, out, /*sel=*/0, /*first=*/1);

    for (int l = 0; l < 3; l++) {
        int insel  = l & 1;
        int outsel = insel ^ 1;
        k_gather<<<(N_NODES * 32 + TB - 1) / TB, TB>>>(insel);
        k_update<<<(N_NODES + 63) / 64, 128>>>(W1, b1, W2, b2, l);
        k_dot<<<(BATCH * 32 + TB - 1) / TB, TB>>>(user, pos, out, outsel, /*first=*/0);
    }
}

// round 13
// speedup vs baseline: 1.4416x; 1.2880x over previous
#include <cuda_runtime.h>
#include <cuda_fp16.h>
#include <cuda_bf16.h>

#define N_USERS 100000
#define N_ITEMS 50000
#define N_NODES 150000
#define KDIM    64
#define N_EDGES 2000000
#define BATCH   4096
#define NEG_SLOPE 0.01f
#define EPSV    1e-12f

#define SCAN_ELEMS 4096
#define SCAN_BLOCKS ((N_NODES + SCAN_ELEMS - 1) / SCAN_ELEMS)   // 37

// ---- HMMA update constants ----
#define UPD_NODES 128
#define UPD_BLOCKS ((N_NODES + UPD_NODES - 1) / UPD_NODES)   // 1172
#define AS_STRIDE 136                         // bf16 elements per smem row (pad)
#define SM_BIAS 0                              // 128 floats = 512 B
#define SM_A    512                            // 128 x AS_STRIDE bf16 = 34816 B
#define SM_B    (512 + 128 * AS_STRIDE * 2)    // 64 x AS_STRIDE bf16 = 17408 B
#define UPD_SMEM (SM_B + 64 * AS_STRIDE * 2)   // 52736 B

typedef unsigned u32;

__device__ __forceinline__ void mma16816(float* d, const u32* a, const u32* b) {
    asm volatile(
        "mma.sync.aligned.m16n8k16.row.col.f32.bf16.bf16.f32 "
        "{%0,%1,%2,%3}, {%4,%5,%6,%7}, {%8,%9}, {%0,%1,%2,%3};"
        : "+f"(d[0]), "+f"(d[1]), "+f"(d[2]), "+f"(d[3])
        : "r"(a[0]), "r"(a[1]), "r"(a[2]), "r"(a[3]), "r"(b[0]), "r"(b[1]));
}

// ---------------- scratch ----------------------------------------------------
__device__ float   g_X[(size_t)N_NODES * KDIM];
__device__ float   g_Y[(size_t)N_NODES * KDIM];
__device__ __half2 g_Xh[(size_t)N_NODES * KDIM / 2];
__device__ __half2 g_Yh[(size_t)N_NODES * KDIM / 2];
__device__ float   g_S[(size_t)N_NODES * KDIM];
__device__ float   g_wsum[N_NODES];
__device__ int     g_cnt[N_NODES];
__device__ int     g_off[N_NODES + 1];
__device__ int     g_fill[N_NODES];
__device__ int2    g_edge[N_EDGES];
__device__ int     g_part[SCAN_BLOCKS];
__device__ int     g_partoff[SCAN_BLOCKS];

// ---------------- init -------------------------------------------------------
__global__ void k_init(const float* __restrict__ Gu, const float* __restrict__ Gi) {
    int i = blockIdx.x * blockDim.x + threadIdx.x;
    const int total  = N_NODES * KDIM / 4;
    const int usplit = N_USERS * KDIM / 4;
    if (i < N_NODES) g_cnt[i] = 0;
    if (i >= total) return;
    float4 v = (i < usplit) ? ((const float4*)Gu)[i] : ((const float4*)Gi)[i - usplit];
    ((float4*)g_X)[i] = v;
    g_Xh[i * 2]     = __floats2half2_rn(v.x, v.y);
    g_Xh[i * 2 + 1] = __floats2half2_rn(v.z, v.w);
}

// ---------------- CSR build --------------------------------------------------
__global__ void k_hist(const int* __restrict__ dst) {
    int t = blockIdx.x * blockDim.x + threadIdx.x;
    int e = t * 8;
    if (e + 7 < N_EDGES) {
        int4 a4 = *(const int4*)&dst[e];
        int4 b4 = *(const int4*)&dst[e + 4];
        atomicAdd(&g_cnt[a4.x], 1);
        atomicAdd(&g_cnt[a4.y], 1);
        atomicAdd(&g_cnt[a4.z], 1);
        atomicAdd(&g_cnt[a4.w], 1);
        atomicAdd(&g_cnt[b4.x], 1);
        atomicAdd(&g_cnt[b4.y], 1);
        atomicAdd(&g_cnt[b4.z], 1);
        atomicAdd(&g_cnt[b4.w], 1);
    } else {
        for (int i = e; i < N_EDGES; i++) atomicAdd(&g_cnt[dst[i]], 1);
    }
}

__global__ void __launch_bounds__(1024) k_part() {
    __shared__ int red[32];
    int tid = threadIdx.x;
    int base = blockIdx.x * SCAN_ELEMS + tid * 4;
    int s = 0;
#pragma unroll
    for (int j = 0; j < 4; j++) {
        int g = base + j;
        s += (g < N_NODES) ? g_cnt[g] : 0;
    }
#pragma unroll
    for (int o = 16; o; o >>= 1) s += __shfl_xor_sync(0xffffffffu, s, o);
    if ((tid & 31) == 0) red[tid >> 5] = s;
    __syncthreads();
    if (tid < 32) {
        int v = red[tid];
#pragma unroll
        for (int o = 16; o; o >>= 1) v += __shfl_xor_sync(0xffffffffu, v, o);
        if (tid == 0) g_part[blockIdx.x] = v;
    }
}

__global__ void k_scanpart() {
    __shared__ int s[64];
    int tid = threadIdx.x;
    int v = (tid < SCAN_BLOCKS) ? g_part[tid] : 0;
    s[tid] = v;
    __syncthreads();
#pragma unroll
    for (int o = 1; o < 64; o <<= 1) {
        int t = (tid >= o) ? s[tid - o] : 0;
        __syncthreads();
        s[tid] += t;
        __syncthreads();
    }
    if (tid < SCAN_BLOCKS) g_partoff[tid] = s[tid] - v;
    if (tid == 63) g_off[N_NODES] = s[63];
}

__global__ void __launch_bounds__(1024) k_scanfinal() {
    __shared__ int wsm[33];
    int tid = threadIdx.x;
    int lane = tid & 31, wid = tid >> 5;
    int base = blockIdx.x * SCAN_ELEMS + tid * 4;
    int v[4];
    int t = 0;
#pragma unroll
    for (int j = 0; j < 4; j++) {
        int g = base + j;
        v[j] = (g < N_NODES) ? g_cnt[g] : 0;
        t += v[j];
    }
    int inc = t;
#pragma unroll
    for (int o = 1; o < 32; o <<= 1) {
        int u = __shfl_up_sync(0xffffffffu, inc, o);
        if (lane >= o) inc += u;
    }
    if (lane == 31) wsm[wid] = inc;
    __syncthreads();
    if (wid == 0) {
        int w = wsm[lane];
        int wi = w;
#pragma unroll
        for (int o = 1; o < 32; o <<= 1) {
            int u = __shfl_up_sync(0xffffffffu, wi, o);
            if (lane >= o) wi += u;
        }
        wsm[lane] = wi - w;
    }
    __syncthreads();
    int excl = g_partoff[blockIdx.x] + wsm[wid] + inc - t;
#pragma unroll
    for (int j = 0; j < 4; j++) {
        int g = base + j;
        if (g < N_NODES) { g_off[g] = excl; g_fill[g] = excl; }
        excl += v[j];
    }
}

__global__ void k_fill(const int* __restrict__ src, const int* __restrict__ dst,
                       const float* __restrict__ ew) {
    int t = blockIdx.x * blockDim.x + threadIdx.x;
    int e = t * 8;
    if (e + 7 < N_EDGES) {
        int4   sa = *(const int4*)&src[e];
        int4   sb = *(const int4*)&src[e + 4];
        int4   da = *(const int4*)&dst[e];
        int4   db = *(const int4*)&dst[e + 4];
        float4 wa = *(const float4*)&ew[e];
        float4 wb = *(const float4*)&ew[e + 4];
        int p0 = atomicAdd(&g_fill[da.x], 1);
        int p1 = atomicAdd(&g_fill[da.y], 1);
        int p2 = atomicAdd(&g_fill[da.z], 1);
        int p3 = atomicAdd(&g_fill[da.w], 1);
        int p4 = atomicAdd(&g_fill[db.x], 1);
        int p5 = atomicAdd(&g_fill[db.y], 1);
        int p6 = atomicAdd(&g_fill[db.z], 1);
        int p7 = atomicAdd(&g_fill[db.w], 1);
        g_edge[p0] = make_int2(sa.x, __float_as_int(wa.x));
        g_edge[p1] = make_int2(sa.y, __float_as_int(wa.y));
        g_edge[p2] = make_int2(sa.z, __float_as_int(wa.z));
        g_edge[p3] = make_int2(sa.w, __float_as_int(wa.w));
        g_edge[p4] = make_int2(sb.x, __float_as_int(wb.x));
        g_edge[p5] = make_int2(sb.y, __float_as_int(wb.y));
        g_edge[p6] = make_int2(sb.z, __float_as_int(wb.z));
        g_edge[p7] = make_int2(sb.w, __float_as_int(wb.w));
    } else {
        for (int i = e; i < N_EDGES; i++) {
            int p = atomicAdd(&g_fill[dst[i]], 1);
            g_edge[p] = make_int2(src[i], __float_as_int(ew[i]));
        }
    }
}

// ---------------- per-layer gather over fp16 mirror --------------------------
__global__ void k_gather(int insel) {
    const __half2* __restrict__ X = insel ? g_Yh : g_Xh;
    int gthr = blockIdx.x * blockDim.x + threadIdx.x;
    int n = gthr >> 5;
    if (n >= N_NODES) return;
    int lane = threadIdx.x & 31;
    int b = g_off[n], e = g_off[n + 1];
    float ax = 0.0f, ay = 0.0f, wa = 0.0f;
    int i = b;
    for (; i + 3 < e; i += 4) {
        int2 E0 = g_edge[i];
        int2 E1 = g_edge[i + 1];
        int2 E2 = g_edge[i + 2];
        int2 E3 = g_edge[i + 3];
        float2 v0 = __half22float2(X[(size_t)E0.x * 32 + lane]);
        float2 v1 = __half22float2(X[(size_t)E1.x * 32 + lane]);
        float2 v2 = __half22float2(X[(size_t)E2.x * 32 + lane]);
        float2 v3 = __half22float2(X[(size_t)E3.x * 32 + lane]);
        float w0 = __int_as_float(E0.y), w1 = __int_as_float(E1.y);
        float w2 = __int_as_float(E2.y), w3 = __int_as_float(E3.y);
        ax += w0 * v0.x + w1 * v1.x + w2 * v2.x + w3 * v3.x;
        ay += w0 * v0.y + w1 * v1.y + w2 * v2.y + w3 * v3.y;
        wa += w0 + w1 + w2 + w3;
    }
    for (; i < e; i++) {
        int2 E0 = g_edge[i];
        float w0 = __int_as_float(E0.y);
        float2 v0 = __half22float2(X[(size_t)E0.x * 32 + lane]);
        ax += w0 * v0.x;
        ay += w0 * v0.y;
        wa += w0;
    }
    *(float2*)&g_S[(size_t)n * KDIM + lane * 2] = make_float2(ax, ay);
    if (insel == 0 && lane == 0) g_wsum[n] = wa;
}

// ---------------- per-layer update via mma.sync bf16 HMMA --------------------
// D[128,64] = A[128,128] x B[64,128]^T, A=[a|b], B rows = output cols.
__global__ void __launch_bounds__(128) k_update(
    const float* __restrict__ W1, const float* __restrict__ b1,
    const float* __restrict__ W2, const float* __restrict__ b2,
    int l) {
    extern __shared__ char smem[];
    float* sBias = (float*)(smem + SM_BIAS);
    __nv_bfloat16* As = (__nv_bfloat16*)(smem + SM_A);
    __nv_bfloat16* Bs = (__nv_bfloat16*)(smem + SM_B);

    const float* __restrict__ Xin = (l & 1) ? g_Y : g_X;
    float* __restrict__ Yout      = (l & 1) ? g_X : g_Y;
    __half2* __restrict__ Yh      = (l & 1) ? g_Xh : g_Yh;
    const float* W1l = W1 + l * 4096;
    const float* W2l = W2 + l * 4096;

    int tid = threadIdx.x;
    int node0 = blockIdx.x * UPD_NODES;

    // ---- stage A: As[node][k] ; k<64: a=s+x, k>=64: b=s*x ----
    {
        int t16 = tid & 15, grp = tid >> 4;
        int c = t16 * 4;
#pragma unroll
        for (int m = 0; m < 16; m++) {
            int nl = grp * 16 + m;
            int n = node0 + nl;
            float4 a4, b4;
            if (n < N_NODES) {
                float4 sv = *(const float4*)&g_S[(size_t)n * KDIM + c];
                float4 xv = *(const float4*)&Xin[(size_t)n * KDIM + c];
                a4 = make_float4(sv.x + xv.x, sv.y + xv.y, sv.z + xv.z, sv.w + xv.w);
                b4 = make_float4(sv.x * xv.x, sv.y * xv.y, sv.z * xv.z, sv.w * xv.w);
            } else {
                a4 = make_float4(0.f, 0.f, 0.f, 0.f);
                b4 = a4;
            }
            __nv_bfloat162* row = (__nv_bfloat162*)&As[nl * AS_STRIDE];
            row[(c >> 1)]          = __floats2bfloat162_rn(a4.x, a4.y);
            row[(c >> 1) + 1]      = __floats2bfloat162_rn(a4.z, a4.w);
            row[(c >> 1) + 32]     = __floats2bfloat162_rn(b4.x, b4.y);
            row[(c >> 1) + 33]     = __floats2bfloat162_rn(b4.z, b4.w);
        }
    }

    // ---- stage B: Bs[n][k] = W1[k][n] (k<64) / W2[k-64][n] ----
#pragma unroll
    for (int p = 0; p < 8; p++) {
        int j = p * 128 + tid;                 // float4 index in W (0..1023)
        int k = j >> 4;
        int n0 = (j & 15) * 4;
        float4 w = ((const float4*)W1l)[j];
        Bs[(n0 + 0) * AS_STRIDE + k] = __float2bfloat16(w.x);
        Bs[(n0 + 1) * AS_STRIDE + k] = __float2bfloat16(w.y);
        Bs[(n0 + 2) * AS_STRIDE + k] = __float2bfloat16(w.z);
        Bs[(n0 + 3) * AS_STRIDE + k] = __float2bfloat16(w.w);
        float4 w2 = ((const float4*)W2l)[j];
        Bs[(n0 + 0) * AS_STRIDE + 64 + k] = __float2bfloat16(w2.x);
        Bs[(n0 + 1) * AS_STRIDE + 64 + k] = __float2bfloat16(w2.y);
        Bs[(n0 + 2) * AS_STRIDE + 64 + k] = __float2bfloat16(w2.z);
        Bs[(n0 + 3) * AS_STRIDE + 64 + k] = __float2bfloat16(w2.w);
    }

    sBias[tid] = (tid < 64) ? b1[l * 64 + tid] : b2[l * 64 + (tid - 64)];
    __syncthreads();

    // ---- mma mainloop ----
    int warp = tid >> 5, lane = tid & 31;
    int g = lane >> 2;                   // fragment row within 8
    int c0 = (lane & 3) * 2;             // fragment col pair
    int m_base = warp * 32;

    float acc[2][8][4];
#pragma unroll
    for (int mt = 0; mt < 2; mt++)
#pragma unroll
        for (int nt = 0; nt < 8; nt++)
#pragma unroll
            for (int q = 0; q < 4; q++) acc[mt][nt][q] = 0.0f;

#pragma unroll
    for (int kt = 0; kt < 8; kt++) {
        int kb = kt * 16;
        u32 a[2][4];
#pragma unroll
        for (int mt = 0; mt < 2; mt++) {
            int r0 = m_base + mt * 16 + g;
            a[mt][0] = *(const u32*)&As[r0 * AS_STRIDE + kb + c0];
            a[mt][1] = *(const u32*)&As[(r0 + 8) * AS_STRIDE + kb + c0];
            a[mt][2] = *(const u32*)&As[r0 * AS_STRIDE + kb + 8 + c0];
            a[mt][3] = *(const u32*)&As[(r0 + 8) * AS_STRIDE + kb + 8 + c0];
        }
#pragma unroll
        for (int nt = 0; nt < 8; nt++) {
            int nrow = nt * 8 + g;
            u32 b[2];
            b[0] = *(const u32*)&Bs[nrow * AS_STRIDE + kb + c0];
            b[1] = *(const u32*)&Bs[nrow * AS_STRIDE + kb + 8 + c0];
            mma16816(acc[0][nt], a[0], b);
            mma16816(acc[1][nt], a[1], b);
        }
    }

    // ---- epilogue: bias + LeakyReLU + row L2 norm + stores ----
#pragma unroll
    for (int mt = 0; mt < 2; mt++) {
        int rl = node0 + m_base + mt * 16 + g;
        int rh = rl + 8;
        float wsl = (rl < N_NODES) ? g_wsum[rl] : 0.0f;
        float wsh = (rh < N_NODES) ? g_wsum[rh] : 0.0f;
        float ssl = 0.0f, ssh = 0.0f;
#pragma unroll
        for (int nt = 0; nt < 8; nt++) {
            int cA = nt * 8 + c0;
            float b1a = sBias[cA], b1b = sBias[cA + 1];
            float b2a = sBias[64 + cA], b2b = sBias[64 + cA + 1];
            float v0 = acc[mt][nt][0] + (wsl + 1.0f) * b1a + wsl * b2a;
            float v1 = acc[mt][nt][1] + (wsl + 1.0f) * b1b + wsl * b2b;
            float v2 = acc[mt][nt][2] + (wsh + 1.0f) * b1a + wsh * b2a;
            float v3 = acc[mt][nt][3] + (wsh + 1.0f) * b1b + wsh * b2b;
            v0 = v0 > 0.0f ? v0 : NEG_SLOPE * v0;
            v1 = v1 > 0.0f ? v1 : NEG_SLOPE * v1;
            v2 = v2 > 0.0f ? v2 : NEG_SLOPE * v2;
            v3 = v3 > 0.0f ? v3 : NEG_SLOPE * v3;
            acc[mt][nt][0] = v0; acc[mt][nt][1] = v1;
            acc[mt][nt][2] = v2; acc[mt][nt][3] = v3;
            ssl += v0 * v0 + v1 * v1;
            ssh += v2 * v2 + v3 * v3;
        }
        ssl += __shfl_xor_sync(0xffffffffu, ssl, 1);
        ssl += __shfl_xor_sync(0xffffffffu, ssl, 2);
        ssh += __shfl_xor_sync(0xffffffffu, ssh, 1);
        ssh += __shfl_xor_sync(0xffffffffu, ssh, 2);
        float invl = 1.0f / fmaxf(sqrtf(ssl), EPSV);
        float invh = 1.0f / fmaxf(sqrtf(ssh), EPSV);
#pragma unroll
        for (int nt = 0; nt < 8; nt++) {
            int cA = nt * 8 + c0;
            if (rl < N_NODES) {
                float y0 = acc[mt][nt][0] * invl;
                float y1 = acc[mt][nt][1] * invl;
                *(float2*)&Yout[(size_t)rl * KDIM + cA] = make_float2(y0, y1);
                Yh[(size_t)rl * 32 + (cA >> 1)] = __floats2half2_rn(y0, y1);
            }
            if (rh < N_NODES) {
                float y2 = acc[mt][nt][2] * invh;
                float y3 = acc[mt][nt][3] * invh;
                *(float2*)&Yout[(size_t)rh * KDIM + cA] = make_float2(y2, y3);
                Yh[(size_t)rh * 32 + (cA >> 1)] = __floats2half2_rn(y2, y3);
            }
        }
    }
}

// ---------------- incremental batch dot --------------------------------------
__global__ void k_dot(const int* __restrict__ user, const int* __restrict__ pos,
                      float* __restrict__ out, int sel, int first) {
    const float* __restrict__ X = sel ? g_Y : g_X;
    int gthr = blockIdx.x * blockDim.x + threadIdx.x;
    int w = gthr >> 5;
    if (w >= BATCH) return;
    int lane = threadIdx.x & 31;
    int u  = user[w];
    int it = pos[w];
    float2 a = *(const float2*)&X[(size_t)u * KDIM + lane * 2];
    float2 b = *(const float2*)&X[((size_t)N_USERS + it) * KDIM + lane * 2];
    float d = a.x * b.x + a.y * b.y;
    d += __shfl_xor_sync(0xffffffffu, d, 16);
    d += __shfl_xor_sync(0xffffffffu, d, 8);
    d += __shfl_xor_sync(0xffffffffu, d, 4);
    d += __shfl_xor_sync(0xffffffffu, d, 2);
    d += __shfl_xor_sync(0xffffffffu, d, 1);
    if (lane == 0) out[w] = first ? d : out[w] + d;
}

// ---------------- launch -------------------------------------------------------
extern "C" void kernel_launch(void* const* d_in, const int* in_sizes, int n_in,
                              void* d_out, int out_size) {
    const float* Gu   = (const float*)d_in[0];
    const float* Gi   = (const float*)d_in[1];
    const float* W1   = (const float*)d_in[2];
    const float* b1   = (const float*)d_in[3];
    const float* W2   = (const float*)d_in[4];
    const float* b2   = (const float*)d_in[5];
    const float* ew   = (const float*)d_in[6];
    const int*   esrc = (const int*)d_in[7];
    const int*   edst = (const int*)d_in[8];
    const int*   user = (const int*)d_in[9];
    const int*   pos  = (const int*)d_in[10];
    float* out = (float*)d_out;

    cudaFuncSetAttribute(k_update, cudaFuncAttributeMaxDynamicSharedMemorySize,
                         UPD_SMEM);

    const int TB = 256;
    k_init<<<(N_NODES * KDIM / 4 + TB - 1) / TB, TB>>>(Gu, Gi);
    k_hist<<<(N_EDGES / 8 + TB - 1) / TB, TB>>>(edst);
    k_part<<<SCAN_BLOCKS, 1024>>>();
    k_scanpart<<<1, 64>>>();
    k_scanfinal<<<SCAN_BLOCKS, 1024>>>();
    k_fill<<<(N_EDGES / 8 + TB - 1) / TB, TB>>>(esrc, edst, ew);

    k_dot<<<(BATCH * 32 + TB - 1) / TB, TB>>>(user, pos, out, /*sel=*/0, /*first=*/1);

    for (int l = 0; l < 3; l++) {
        int insel  = l & 1;
        int outsel = insel ^ 1;
        k_gather<<<(N_NODES * 32 + TB - 1) / TB, TB>>>(insel);
        k_update<<<UPD_BLOCKS, 128, UPD_SMEM>>>(W1, b1, W2, b2, l);
        k_dot<<<(BATCH * 32 + TB - 1) / TB, TB>>>(user, pos, out, outsel, /*first=*/0);
    }
}